// round 1
// baseline (speedup 1.0000x reference)
#include <cuda_runtime.h>
#include <math.h>

#define S_LEN   2048
#define D_MODEL 1024
#define NH      16
#define DH      64
#define BATCH   2
#define M_ROWS  (BATCH * S_LEN)   // 4096

// ---------------------------------------------------------------------------
// Scratch (device globals: allocation-free, graph-capture safe)
// ---------------------------------------------------------------------------
__device__ float g_q[M_ROWS * D_MODEL];
__device__ float g_k[M_ROWS * D_MODEL];
__device__ float g_v[M_ROWS * D_MODEL];
__device__ float g_att[M_ROWS * D_MODEL];

// ---------------------------------------------------------------------------
// SGEMM: Y[M,N] = X[M,K] @ W[N,K]^T   (torch Linear convention)
// BM=BN=64, BK=16, 256 threads, 4x4 micro-tile per thread.
// ---------------------------------------------------------------------------
__global__ __launch_bounds__(256) void sgemm_xwT(
    const float* __restrict__ X, const float* __restrict__ W,
    float* __restrict__ Y, int M, int N, int K)
{
    __shared__ __align__(16) float Xs[16][68];   // [k][m], padded row = 272B (16B mult)
    __shared__ __align__(16) float Ws[16][68];   // [k][n]

    const int tid  = threadIdx.x;
    const int tx   = tid & 15;        // 0..15 -> N micro
    const int ty   = tid >> 4;        // 0..15 -> M micro
    const int row0 = blockIdx.y * 64;
    const int col0 = blockIdx.x * 64;

    // Cooperative loads: one float4 per thread per operand per k-tile
    const int lr = tid >> 2;          // 0..63 tile row
    const int lk = (tid & 3) * 4;     // 0,4,8,12 along K
    const float* Xp = X + (size_t)(row0 + lr) * K + lk;
    const float* Wp = W + (size_t)(col0 + lr) * K + lk;

    float acc[4][4] = {};

    for (int k0 = 0; k0 < K; k0 += 16) {
        float4 xv = *(const float4*)(Xp + k0);
        float4 wv = *(const float4*)(Wp + k0);
        Xs[lk + 0][lr] = xv.x; Xs[lk + 1][lr] = xv.y;
        Xs[lk + 2][lr] = xv.z; Xs[lk + 3][lr] = xv.w;
        Ws[lk + 0][lr] = wv.x; Ws[lk + 1][lr] = wv.y;
        Ws[lk + 2][lr] = wv.z; Ws[lk + 3][lr] = wv.w;
        __syncthreads();

        #pragma unroll
        for (int k = 0; k < 16; k++) {
            float4 a = *(const float4*)&Xs[k][ty * 4];
            float4 b = *(const float4*)&Ws[k][tx * 4];
            float ar[4] = {a.x, a.y, a.z, a.w};
            float br[4] = {b.x, b.y, b.z, b.w};
            #pragma unroll
            for (int i = 0; i < 4; i++)
                #pragma unroll
                for (int j = 0; j < 4; j++)
                    acc[i][j] = fmaf(ar[i], br[j], acc[i][j]);
        }
        __syncthreads();
    }

    #pragma unroll
    for (int i = 0; i < 4; i++) {
        float4 o = make_float4(acc[i][0], acc[i][1], acc[i][2], acc[i][3]);
        *(float4*)(Y + (size_t)(row0 + ty * 4 + i) * N + col0 + tx * 4) = o;
    }
}

// ---------------------------------------------------------------------------
// Flash attention (causal), fp32. One block per (q-tile=64, head, batch).
// 256 threads, 16x16 grid, each thread owns a 4x4 patch of the 64x64 score
// tile and a 4x4 patch of the 64x64 output tile. Q/K staged d-major in smem,
// P staged through smem for the PV product.
// ---------------------------------------------------------------------------
__global__ __launch_bounds__(256) void attn_fwd(
    const float* __restrict__ Qg, const float* __restrict__ Kg,
    const float* __restrict__ Vg, float* __restrict__ Og)
{
    extern __shared__ __align__(16) float smem[];
    float (*Qs)[68] = (float(*)[68])(smem);              // [d][i]
    float (*Ks)[68] = (float(*)[68])(smem + 1 * 64 * 68);// [d][j]
    float (*Vs)[68] = (float(*)[68])(smem + 2 * 64 * 68);// [j][c]
    float (*Ps)[68] = (float(*)[68])(smem + 3 * 64 * 68);// [i][j]

    const int tid = threadIdx.x;
    const int tx  = tid & 15;          // key / out-col micro
    const int ty  = tid >> 4;          // query-row micro
    const int qt  = blockIdx.x;
    const int q0  = qt * 64;
    const int h   = blockIdx.y;
    const int b   = blockIdx.z;

    const float* Qb = Qg + ((size_t)b * S_LEN + q0) * D_MODEL + h * DH;
    const float* Kb = Kg + (size_t)b * S_LEN * D_MODEL + h * DH;
    const float* Vb = Vg + (size_t)b * S_LEN * D_MODEL + h * DH;

    // Load Q tile transposed (d-major) with the 1/sqrt(DH) scale folded in
    #pragma unroll
    for (int r = 0; r < 4; r++) {
        int idx = tid + r * 256;           // 0..1023 float4 slots
        int row = idx >> 4;                // 0..63
        int c4  = (idx & 15) * 4;          // 0..60
        float4 qv = *(const float4*)(Qb + (size_t)row * D_MODEL + c4);
        Qs[c4 + 0][row] = qv.x * 0.125f;
        Qs[c4 + 1][row] = qv.y * 0.125f;
        Qs[c4 + 2][row] = qv.z * 0.125f;
        Qs[c4 + 3][row] = qv.w * 0.125f;
    }

    float m_i[4], l_i[4], o[4][4];
    #pragma unroll
    for (int i = 0; i < 4; i++) {
        m_i[i] = -INFINITY; l_i[i] = 0.f;
        #pragma unroll
        for (int j = 0; j < 4; j++) o[i][j] = 0.f;
    }

    for (int kt = 0; kt <= qt; kt++) {
        const int k0 = kt * 64;
        __syncthreads();   // previous iteration's Ps/Vs reads complete

        // Load K (transposed, d-major) and V (row-major) tiles
        #pragma unroll
        for (int r = 0; r < 4; r++) {
            int idx = tid + r * 256;
            int row = idx >> 4;
            int c4  = (idx & 15) * 4;
            float4 kv = *(const float4*)(Kb + (size_t)(k0 + row) * D_MODEL + c4);
            Ks[c4 + 0][row] = kv.x; Ks[c4 + 1][row] = kv.y;
            Ks[c4 + 2][row] = kv.z; Ks[c4 + 3][row] = kv.w;
            float4 vv = *(const float4*)(Vb + (size_t)(k0 + row) * D_MODEL + c4);
            *(float4*)&Vs[row][c4] = vv;
        }
        __syncthreads();

        // S = (Q*scale) @ K^T  : 4x4 per thread
        float s[4][4] = {};
        #pragma unroll
        for (int d = 0; d < 64; d++) {
            float4 qa = *(const float4*)&Qs[d][ty * 4];
            float4 kb = *(const float4*)&Ks[d][tx * 4];
            float ar[4] = {qa.x, qa.y, qa.z, qa.w};
            float br[4] = {kb.x, kb.y, kb.z, kb.w};
            #pragma unroll
            for (int i = 0; i < 4; i++)
                #pragma unroll
                for (int j = 0; j < 4; j++)
                    s[i][j] = fmaf(ar[i], br[j], s[i][j]);
        }

        // Causal mask only matters on the diagonal tile
        if (kt == qt) {
            #pragma unroll
            for (int i = 0; i < 4; i++)
                #pragma unroll
                for (int j = 0; j < 4; j++)
                    if (tx * 4 + j > ty * 4 + i) s[i][j] = -INFINITY;
        }

        // Online softmax update (row reduction across the 16 tx lanes)
        #pragma unroll
        for (int i = 0; i < 4; i++) {
            float mloc = fmaxf(fmaxf(s[i][0], s[i][1]), fmaxf(s[i][2], s[i][3]));
            #pragma unroll
            for (int off = 1; off < 16; off <<= 1)
                mloc = fmaxf(mloc, __shfl_xor_sync(0xffffffffu, mloc, off));
            float mnew  = fmaxf(m_i[i], mloc);
            float alpha = expf(m_i[i] - mnew);   // expf(-inf)=0 on first tile
            float psum = 0.f;
            #pragma unroll
            for (int j = 0; j < 4; j++) {
                float p = expf(s[i][j] - mnew);  // masked entries -> 0
                s[i][j] = p;
                psum += p;
            }
            #pragma unroll
            for (int off = 1; off < 16; off <<= 1)
                psum += __shfl_xor_sync(0xffffffffu, psum, off);
            l_i[i] = l_i[i] * alpha + psum;
            m_i[i] = mnew;
            #pragma unroll
            for (int j = 0; j < 4; j++) o[i][j] *= alpha;
            *(float4*)&Ps[ty * 4 + i][tx * 4] =
                make_float4(s[i][0], s[i][1], s[i][2], s[i][3]);
        }
        __syncthreads();

        // O += P @ V   (P broadcast from smem, V as float4 rows)
        #pragma unroll
        for (int j = 0; j < 64; j++) {
            float4 vv = *(const float4*)&Vs[j][tx * 4];
            #pragma unroll
            for (int i = 0; i < 4; i++) {
                float p = Ps[ty * 4 + i][j];
                o[i][0] = fmaf(p, vv.x, o[i][0]);
                o[i][1] = fmaf(p, vv.y, o[i][1]);
                o[i][2] = fmaf(p, vv.z, o[i][2]);
                o[i][3] = fmaf(p, vv.w, o[i][3]);
            }
        }
    }

    // Normalize and store (layout [B][S][D] so the Wo GEMM is standard)
    float* Ob = Og + ((size_t)b * S_LEN + q0) * D_MODEL + h * DH;
    #pragma unroll
    for (int i = 0; i < 4; i++) {
        float inv = 1.f / l_i[i];
        float4 ov = make_float4(o[i][0] * inv, o[i][1] * inv,
                                o[i][2] * inv, o[i][3] * inv);
        *(float4*)(Ob + (size_t)(ty * 4 + i) * D_MODEL + tx * 4) = ov;
    }
}

// ---------------------------------------------------------------------------
// Launch
// ---------------------------------------------------------------------------
extern "C" void kernel_launch(void* const* d_in, const int* in_sizes, int n_in,
                              void* d_out, int out_size)
{
    const float* x  = (const float*)d_in[0];
    const float* Wq = (const float*)d_in[1];
    const float* Wk = (const float*)d_in[2];
    const float* Wv = (const float*)d_in[3];
    const float* Wo = (const float*)d_in[4];
    float* out = (float*)d_out;

    float *q, *k, *v, *att;
    cudaGetSymbolAddress((void**)&q,   g_q);
    cudaGetSymbolAddress((void**)&k,   g_k);
    cudaGetSymbolAddress((void**)&v,   g_v);
    cudaGetSymbolAddress((void**)&att, g_att);

    dim3 gg(D_MODEL / 64, M_ROWS / 64);   // (16, 64)
    sgemm_xwT<<<gg, 256>>>(x, Wq, q, M_ROWS, D_MODEL, D_MODEL);
    sgemm_xwT<<<gg, 256>>>(x, Wk, k, M_ROWS, D_MODEL, D_MODEL);
    sgemm_xwT<<<gg, 256>>>(x, Wv, v, M_ROWS, D_MODEL, D_MODEL);

    const size_t smem = 4 * 64 * 68 * sizeof(float);  // 69632 B
    cudaFuncSetAttribute(attn_fwd, cudaFuncAttributeMaxDynamicSharedMemorySize,
                         (int)smem);
    attn_fwd<<<dim3(S_LEN / 64, NH, BATCH), 256, smem>>>(q, k, v, att);

    sgemm_xwT<<<gg, 256>>>(att, Wo, out, M_ROWS, D_MODEL, D_MODEL);
}